// round 15
// baseline (speedup 1.0000x reference)
#include <cuda_runtime.h>
#include <cuda_bf16.h>
#include <cstdint>

#define BATCH 16
#define MP 30      // max people
#define NJ 17      // joints
#define AD 17      // ae tag dim
#define RES 512
#define RR (RES*RES)

#define JPI   (MP * NJ)        // 510 joints per image
#define EPI   (JPI * AD)       // 8670 elements per image
#define CSZ   8                // cluster size (CTAs per image)
#define PER_RANK 1084          // ceil(8670/8)
#define BT    512
#define NPAIR 435              // MP*(MP-1)/2 unordered pairs

__device__ __forceinline__ uint32_t smem_u32(const void* p) {
    uint32_t a;
    asm("{ .reg .u64 t; cvta.to.shared.u64 t, %1; cvt.u32.u64 %0, t; }"
        : "=r"(a) : "l"(p));
    return a;
}
__device__ __forceinline__ uint32_t my_cluster_rank() {
    uint32_t r;
    asm("mov.u32 %0, %%cluster_ctarank;" : "=r"(r));
    return r;
}

__global__ __launch_bounds__(BT, 1) __cluster_dims__(CSZ, 1, 1)
void ae_cluster_kernel(const float* __restrict__ tags,
                       const int*   __restrict__ joints,
                       float*       __restrict__ out)
{
    const int tid  = threadIdx.x;
    const int b    = blockIdx.x / CSZ;          // image = cluster id
    const uint32_t rank = my_cluster_rank();
    const unsigned FULL = 0xffffffffu;

    // rank-0's copy holds the full gathered tag matrix [JPI][AD]
    __shared__ float sh_tags[JPI * AD];         // 34.7 KB
    __shared__ float sqj[JPI];
    __shared__ float validv[JPI];
    __shared__ float rcnt[MP];
    __shared__ float cntv[MP];
    __shared__ float pv[MP];
    __shared__ float sqp[MP];
    __shared__ float mean_s[MP][AD];
    __shared__ float ntags_s;
    __shared__ float push_acc;

    // ---------- Phase A: all 8 ranks gather their slice, push to rank 0 ----
    {
        const int base = (int)rank * PER_RANK;
        const int lim  = (base + PER_RANK < EPI) ? base + PER_RANK : EPI;
        #pragma unroll
        for (int k = 0; k < 3; k++) {
            const int e = base + tid + k * BT;
            if (e < lim) {
                const int jl = e / AD;          // joint within image
                const int d  = e % AD;
                const int jj = b * JPI + jl;

                const int idx = __ldg(&joints[jj * 2 + 0]);
                const int vis = __ldg(&joints[jj * 2 + 1]);

                float v = 0.0f;
                if (vis > 0) {
                    int off = idx % RR;
                    if (off < 0) off += RR;
                    const int x = off % RES;    // first spatial axis (torch convention)
                    const int y = off / RES;
                    v = __ldg(tags + (size_t)b * AD * RR + (size_t)d * RR
                                   + (size_t)x * RES + y);
                }
                // store masked value into rank 0's smem
                uint32_t laddr = smem_u32(&sh_tags[jl * AD + d]);
                uint32_t raddr;
                asm("mapa.shared::cluster.u32 %0, %1, %2;"
                    : "=r"(raddr) : "r"(laddr), "r"(0));
                asm volatile("st.shared::cluster.f32 [%0], %1;"
                             :: "r"(raddr), "f"(v) : "memory");
            }
        }
    }

    // cluster barrier: release all DSMEM stores, acquire before rank0 reads
    asm volatile("barrier.cluster.arrive.aligned;" ::: "memory");
    asm volatile("barrier.cluster.wait.aligned;"   ::: "memory");

    if (rank != 0) return;                      // producers done

    // ---------- Phase B (rank 0 only): lean reduce from own smem ----------
    if (tid == 0) push_acc = 0.0f;

    // per-joint s1/s2 (masked values => exact 0 for invisible joints)
    if (tid < JPI) {
        const float* row = &sh_tags[tid * AD];
        float s1 = 0.0f, s2 = 0.0f;
        #pragma unroll
        for (int d = 0; d < AD; d++) {
            const float v = row[d];
            s1 += v;
            s2 += v * v;
        }
        sqj[tid]    = 2.0f * (float)AD * s2 - 2.0f * s1 * s1;
        validv[tid] = (__ldg(&joints[(b * JPI + tid) * 2 + 1]) > 0) ? 1.0f : 0.0f;
    }
    __syncthreads();

    // per-person cnt/sq + one reciprocal each
    if (tid < MP) {
        float cnt = 0.0f, sq = 0.0f;
        #pragma unroll
        for (int j = 0; j < NJ; j++) {
            cnt += validv[tid * NJ + j];
            sq  += sqj[tid * NJ + j];
        }
        cntv[tid] = cnt;
        sqp[tid]  = sq;
        pv[tid]   = (cnt > 0.0f) ? 1.0f : 0.0f;
        rcnt[tid] = 1.0f / fmaxf(cnt, 1.0f);
    }
    __syncthreads();

    // means: one thread per (m,d), smem column sums
    if (tid < MP * AD) {
        const int m = tid / AD;
        const int d = tid % AD;
        float s = 0.0f;
        #pragma unroll
        for (int j = 0; j < NJ; j++) s += sh_tags[(m * NJ + j) * AD + d];
        mean_s[m][d] = s * rcnt[m];
    }

    // n_tags + pull on warp 0 (independent of mean phase)
    if (tid < 32) {
        float nt = 0.0f, pl = 0.0f;
        if (tid < MP) {
            nt = pv[tid];
            pl = pv[tid] * sqp[tid] * rcnt[tid] * (1.0f / (float)(AD * AD));
        }
        #pragma unroll
        for (int o = 16; o > 0; o >>= 1) {
            nt += __shfl_down_sync(FULL, nt, o);
            pl += __shfl_down_sync(FULL, pl, o);
        }
        if (tid == 0) {
            ntags_s = nt;
            out[BATCH + b] = pl / fmaxf(nt, 1.0f);   // pull[16]
        }
    }
    __syncthreads();

    // push: 435 unordered pairs, closed-form triangular decode, 17 EX2 each
    float acc = 0.0f;
    if (tid < NPAIR) {
        const int p = tid;
        float disc = (float)((2 * MP - 1) * (2 * MP - 1)) - 8.0f * (float)p;
        int m1 = (int)floorf(((float)(2 * MP - 1) - sqrtf(disc)) * 0.5f);
        if ((m1 + 1) * (2 * MP - 2 - m1) / 2 <= p) m1++;
        if (m1 * (2 * MP - 1 - m1) / 2 > p)        m1--;
        const int m2 = m1 + 1 + (p - m1 * (2 * MP - 1 - m1) / 2);

        if (pv[m1] * pv[m2] != 0.0f) {
            float s = 0.0f;
            #pragma unroll
            for (int d = 0; d < AD; d++) {
                float df = mean_s[m1][d] - mean_s[m2][d];
                s += __expf(-df * df);
            }
            acc = s * (1.0f / (float)AD);
        }
    }
    #pragma unroll
    for (int o = 16; o > 0; o >>= 1)
        acc += __shfl_down_sync(FULL, acc, o);
    if ((tid & 31) == 0 && tid < NPAIR) atomicAdd(&push_acc, acc);
    __syncthreads();

    if (tid == 0) {
        const float nt = ntags_s;
        const float denom = fmaxf(nt, 1.0f);
        // ordered off-diag = 2 * unordered; diagonal sum = nt (exp(0)=1)
        out[b] = (nt >= 2.0f) ? ((2.0f * push_acc + nt) / (denom * denom)) : 0.0f;
    }
}

extern "C" void kernel_launch(void* const* d_in, const int* in_sizes, int n_in,
                              void* d_out, int out_size)
{
    const float* tags   = (const float*)d_in[0];
    const int*   joints = (const int*)d_in[1];
    float*       out    = (float*)d_out;

    ae_cluster_kernel<<<BATCH * CSZ, BT>>>(tags, joints, out);
}

// round 16
// speedup vs baseline: 1.2657x; 1.2657x over previous
#include <cuda_runtime.h>
#include <cuda_bf16.h>

#define BATCH 16
#define MP 30      // max people
#define NJ 17      // joints
#define AD 17      // ae tag dim
#define RES 512
#define RR (RES*RES)

#define JPI (MP * NJ)                    // 510 joints per image
#define NJT (BATCH * JPI)                // 8160 joints total
#define NPT (BATCH * MP)                 // 480 persons total
#define NPAIR 435                        // MP*(MP-1)/2 unordered pairs

// person-level accumulators (zero-init; finalize re-zeroes after consuming)
__device__ float g_psum[NPT * AD];       // per-(person,d) masked tag sums
__device__ float g_sqp [NPT];            // per-person sum of 2D*s2-2*s1^2
__device__ float g_cnt [NPT];            // per-person valid joint count

// ---------------------------------------------------------------------------
// Kernel 1: one joint per warp. Gather 17 channels, shfl-reduce s1/s2,
// RED.ADD person-level stats. Invisible joints: no loads, no atomics.
// ---------------------------------------------------------------------------
__global__ __launch_bounds__(512)
void ae_gather_kernel(const float* __restrict__ tags,
                      const int*   __restrict__ joints)
{
    const unsigned FULL = 0xffffffffu;
    const int lane = threadIdx.x & 31;
    const int jj   = blockIdx.x * 16 + (threadIdx.x >> 5);  // global joint id (510*16 == 8160)
    const int b    = jj / JPI;
    const int pt   = jj / NJ;            // global person id

    const int2 jt = __ldg((const int2*)joints + jj);   // {heatmap idx, vis}

    if (jt.y > 0) {
        int off = jt.x % RR;
        if (off < 0) off += RR;
        const int x = off % RES;         // first spatial axis (torch convention)
        const int y = off / RES;

        float v = 0.0f;
        if (lane < AD)
            v = __ldg(tags + (size_t)b * AD * RR + (size_t)lane * RR
                           + (size_t)x * RES + y);

        float s1 = v, s2 = v * v;
        #pragma unroll
        for (int o = 16; o > 0; o >>= 1) {
            s1 += __shfl_down_sync(FULL, s1, o);
            s2 += __shfl_down_sync(FULL, s2, o);
        }

        if (lane < AD) atomicAdd(&g_psum[pt * AD + lane], v);   // RED, no return
        if (lane == 0) {
            // sum_{d1,d2}(t_d1 - t_d2)^2 = 2*D*S2 - 2*S1^2
            atomicAdd(&g_sqp[pt], 2.0f * (float)AD * s2 - 2.0f * s1 * s1);
            atomicAdd(&g_cnt[pt], 1.0f);
        }
    }
}

// ---------------------------------------------------------------------------
// Kernel 2: thin finalize, one CTA per image; zeroes accumulators afterwards.
// ---------------------------------------------------------------------------
__global__ __launch_bounds__(512, 1)
void ae_final_kernel(float* __restrict__ out)
{
    const int b   = blockIdx.x;
    const int tid = threadIdx.x;
    const unsigned FULL = 0xffffffffu;

    __shared__ float rcnt[MP];
    __shared__ float pv[MP];
    __shared__ float sqp_s[MP];
    __shared__ float mean_s[MP][AD];
    __shared__ float ntags_s;
    __shared__ float push_acc;

    if (tid == 0) push_acc = 0.0f;

    // person stats for this image
    float psv = 0.0f;
    if (tid < MP * AD) psv = g_psum[b * MP * AD + tid];
    if (tid < MP) {
        const float c = g_cnt[b * MP + tid];
        sqp_s[tid] = g_sqp[b * MP + tid];
        pv[tid]    = (c > 0.0f) ? 1.0f : 0.0f;
        rcnt[tid]  = 1.0f / fmaxf(c, 1.0f);
    }
    __syncthreads();

    if (tid < MP * AD)
        mean_s[tid / AD][tid % AD] = psv * rcnt[tid / AD];

    // n_tags + pull on warp 0
    if (tid < 32) {
        float nt = 0.0f, pl = 0.0f;
        if (tid < MP) {
            nt = pv[tid];
            pl = pv[tid] * sqp_s[tid] * rcnt[tid] * (1.0f / (float)(AD * AD));
        }
        #pragma unroll
        for (int o = 16; o > 0; o >>= 1) {
            nt += __shfl_down_sync(FULL, nt, o);
            pl += __shfl_down_sync(FULL, pl, o);
        }
        if (tid == 0) {
            ntags_s = nt;
            out[BATCH + b] = pl / fmaxf(nt, 1.0f);   // pull[16]
        }
    }

    // zero this image's accumulators for the next graph replay
    if (tid < MP * AD) g_psum[b * MP * AD + tid] = 0.0f;
    if (tid < MP) { g_sqp[b * MP + tid] = 0.0f; g_cnt[b * MP + tid] = 0.0f; }
    __syncthreads();

    // push: 435 unordered pairs, closed-form triangular decode, 17 EX2 each
    float acc = 0.0f;
    if (tid < NPAIR) {
        const int p = tid;
        float disc = (float)((2 * MP - 1) * (2 * MP - 1)) - 8.0f * (float)p;
        int m1 = (int)floorf(((float)(2 * MP - 1) - sqrtf(disc)) * 0.5f);
        if ((m1 + 1) * (2 * MP - 2 - m1) / 2 <= p) m1++;
        if (m1 * (2 * MP - 1 - m1) / 2 > p)        m1--;
        const int m2 = m1 + 1 + (p - m1 * (2 * MP - 1 - m1) / 2);

        if (pv[m1] * pv[m2] != 0.0f) {
            float s = 0.0f;
            #pragma unroll
            for (int d = 0; d < AD; d++) {
                float df = mean_s[m1][d] - mean_s[m2][d];
                s += __expf(-df * df);
            }
            acc = s * (1.0f / (float)AD);
        }
    }
    #pragma unroll
    for (int o = 16; o > 0; o >>= 1)
        acc += __shfl_down_sync(FULL, acc, o);
    if ((tid & 31) == 0 && tid < NPAIR) atomicAdd(&push_acc, acc);
    __syncthreads();

    if (tid == 0) {
        const float nt = ntags_s;
        const float denom = fmaxf(nt, 1.0f);
        // ordered off-diag = 2 * unordered; diagonal sum = nt (exp(0)=1)
        out[b] = (nt >= 2.0f) ? ((2.0f * push_acc + nt) / (denom * denom)) : 0.0f;
    }
}

extern "C" void kernel_launch(void* const* d_in, const int* in_sizes, int n_in,
                              void* d_out, int out_size)
{
    const float* tags   = (const float*)d_in[0];
    const int*   joints = (const int*)d_in[1];
    float*       out    = (float*)d_out;

    ae_gather_kernel<<<JPI, 512>>>(tags, joints);   // 510 CTAs, 1 joint/warp
    ae_final_kernel<<<BATCH, 512>>>(out);
}